// round 17
// baseline (speedup 1.0000x reference)
#include <cuda_runtime.h>
#include <math.h>

// Problem constants
#define NBATCH 8
#define NPTS   2048
#define NFEAT  32
#define NROWS  (NBATCH * NPTS)                       // 16384
#define NMAT   ((size_t)NBATCH * NPTS * NPTS)        // 33554432
#define MAX_IT 100

// eps = 0.1 ; log2-domain scale: (1/eps) * log2(e)
#define S2   14.4269504088896341f
#define LN2  0.6931471805599453f
#define EPSV 0.1f
#define LOG_MUV (logf(1.0f / 2048.0f + 1e-8f))      // == log_nu (N == M)
#define ERR_THRESH_SUM 0.8f

// Batches [0, PIN_B) are loaded with L2::evict_last (pinned ~96 MB < 126 MB L2);
// batches [PIN_B, 8) stream with default policy and only evict themselves.
#define PIN_B 6

// Scratch (__device__ globals; no allocation allowed)
__device__ __align__(16) float g_u[NROWS];
__device__ __align__(16) float g_v[NROWS];
__device__ float g_err[MAX_IT];

__device__ __forceinline__ float ex2f(float x) {
    float y;
    asm("ex2.approx.ftz.f32 %0, %1;" : "=f"(y) : "f"(x));
    return y;
}
__device__ __forceinline__ float lg2f(float x) {
    float y;
    asm("lg2.approx.ftz.f32 %0, %1;" : "=f"(y) : "f"(x));
    return y;
}

// 256-bit evict_last load (the ONLY width ptxas accepts with this hint on
// sm_103a): 8 contiguous floats, 32B-aligned.
#define LD8_EL(p, d0, d1, d2, d3, d4, d5, d6, d7)                              \
    asm("ld.global.nc.L2::evict_last.v8.b32 {%0,%1,%2,%3,%4,%5,%6,%7}, [%8];"  \
        : "=f"(d0), "=f"(d1), "=f"(d2), "=f"(d3),                              \
          "=f"(d4), "=f"(d5), "=f"(d6), "=f"(d7)                               \
        : "l"(p))

// ---------------------------------------------------------------------------
// Init
// ---------------------------------------------------------------------------
__global__ void k_init(float* __restrict__ cost) {
    int t = blockIdx.x * blockDim.x + threadIdx.x;
    int n = gridDim.x * blockDim.x;
    for (int i = t; i < NROWS; i += n) {
        g_u[i] = 0.0f;
        g_v[i] = 0.0f;
    }
    if (t < MAX_IT) g_err[t] = 0.0f;
    if (t < NBATCH) cost[t] = 0.0f;
}

// ---------------------------------------------------------------------------
// Cost matrix: C[b,i,j] = sum_d (x[b,i,d] - y[b,j,d])^2
// ---------------------------------------------------------------------------
__global__ void __launch_bounds__(256) k_cost(const float* __restrict__ x,
                                              const float* __restrict__ y,
                                              float* __restrict__ C) {
    __shared__ float xs[NFEAT * 65];
    __shared__ float ys[NFEAT * 65];

    int tile = blockIdx.x;          // 8192 tiles of 64x64
    int b  = tile >> 10;
    int ti = (tile >> 5) & 31;
    int tj = tile & 31;
    int tid = threadIdx.x;

    const float* xb = x + ((size_t)b * NPTS + (size_t)ti * 64) * NFEAT;
    const float* yb = y + ((size_t)b * NPTS + (size_t)tj * 64) * NFEAT;

    for (int e = tid; e < 64 * NFEAT; e += 256) {
        int row = e >> 5;
        int d   = e & 31;
        xs[d * 65 + row] = xb[e];
        ys[d * 65 + row] = yb[e];
    }
    __syncthreads();

    int ri = (tid >> 4) << 2;
    int cj = (tid & 15) << 2;

    float acc[4][4];
#pragma unroll
    for (int a = 0; a < 4; a++)
#pragma unroll
        for (int c = 0; c < 4; c++) acc[a][c] = 0.0f;

#pragma unroll
    for (int d = 0; d < NFEAT; d++) {
        float xa[4], yv[4];
#pragma unroll
        for (int a = 0; a < 4; a++) xa[a] = xs[d * 65 + ri + a];
#pragma unroll
        for (int c = 0; c < 4; c++) yv[c] = ys[d * 65 + cj + c];
#pragma unroll
        for (int a = 0; a < 4; a++)
#pragma unroll
            for (int c = 0; c < 4; c++) {
                float diff = xa[a] - yv[c];
                acc[a][c] = fmaf(diff, diff, acc[a][c]);
            }
    }

    float* Cb = C + (size_t)b * NPTS * NPTS + (size_t)(ti * 64 + ri) * NPTS + (tj * 64 + cj);
#pragma unroll
    for (int a = 0; a < 4; a++) {
        float4 o = make_float4(acc[a][0], acc[a][1], acc[a][2], acc[a][3]);
        *reinterpret_cast<float4*>(Cb + (size_t)a * NPTS) = o;
    }
}

// ---------------------------------------------------------------------------
// u-sweep (row LSE over C, row-major). 2048 blocks x 256 thr, warp per row,
// dual online-LSE chains, one-step register prefetch.
// b < PIN_B: 256-bit evict_last loads (pin those batches in L2).
// b >= PIN_B: plain float4 loads (streaming portion, self-evicting).
// ---------------------------------------------------------------------------
__global__ void __launch_bounds__(256, 5) k_sweep(const float* __restrict__ M,
                                                  const float* __restrict__ oth,
                                                  float* __restrict__ mine,
                                                  int it, int track_err) {
    if (it > 0 && g_err[it - 1] < ERR_THRESH_SUM) return;

    __shared__ float oS2[NPTS];          // 8 KB : other potential * S2
    __shared__ float blkerr;

    int blk = blockIdx.x;                // 2048 blocks, 8 rows each
    int b   = blk >> 8;
    int tid = threadIdx.x;
    int w   = tid >> 5;
    int l   = tid & 31;

    const float4* og  = reinterpret_cast<const float4*>(oth + (b << 11));
    float4*       os4 = reinterpret_cast<float4*>(oS2);
#pragma unroll
    for (int k = 0; k < 2; k++) {
        float4 t = og[tid + (k << 8)];
        t.x *= S2; t.y *= S2; t.z *= S2; t.w *= S2;
        os4[tid + (k << 8)] = t;
    }
    if (tid == 0) blkerr = 0.0f;
    __syncthreads();

    int r = (blk << 3) + w;              // global row index
    float m0 = -1e30f, s0 = 0.0f, m1 = -1e30f, s1 = 0.0f;

    if (b < PIN_B) {
        // ---- evict_last path: 8 contiguous floats per thread per step ----
        const float* Mrow = M + ((size_t)r << 11);
        float p0, p1, p2, p3, p4, p5, p6, p7;
        LD8_EL(Mrow + (l << 3), p0, p1, p2, p3, p4, p5, p6, p7);
#pragma unroll
        for (int g = 0; g < 8; g++) {
            float c0 = p0, c1 = p1, c2 = p2, c3 = p3;
            float c4 = p4, c5 = p5, c6 = p6, c7 = p7;
            if (g < 7) {
                LD8_EL(Mrow + ((g + 1) << 8) + (l << 3),
                       p0, p1, p2, p3, p4, p5, p6, p7);
            }
            int q = (g << 6) + (l << 1);
            float4 v0 = os4[q];
            float4 v1 = os4[q + 1];
            float t0 = fmaf(-S2, c0, v0.x);
            float t1 = fmaf(-S2, c1, v0.y);
            float t2 = fmaf(-S2, c2, v0.z);
            float t3 = fmaf(-S2, c3, v0.w);
            float t4 = fmaf(-S2, c4, v1.x);
            float t5 = fmaf(-S2, c5, v1.y);
            float t6 = fmaf(-S2, c6, v1.z);
            float t7 = fmaf(-S2, c7, v1.w);
            float mA = fmaxf(fmaxf(t0, t1), fmaxf(t2, t3));
            float n0 = fmaxf(m0, mA);
            s0 = s0 * ex2f(m0 - n0)
               + ((ex2f(t0 - n0) + ex2f(t1 - n0)) + (ex2f(t2 - n0) + ex2f(t3 - n0)));
            m0 = n0;
            float mB = fmaxf(fmaxf(t4, t5), fmaxf(t6, t7));
            float n1 = fmaxf(m1, mB);
            s1 = s1 * ex2f(m1 - n1)
               + ((ex2f(t4 - n1) + ex2f(t5 - n1)) + (ex2f(t6 - n1) + ex2f(t7 - n1)));
            m1 = n1;
        }
    } else {
        // ---- streaming path: float4 pairs + register prefetch (R15) ----
        const float4* Mr = reinterpret_cast<const float4*>(M + ((size_t)r << 11));
        float4 p0 = Mr[l];
        float4 p1 = Mr[l + 32];
#pragma unroll
        for (int g = 0; g < 8; g++) {
            int idx = l + (g << 6);
            float4 c0 = p0;
            float4 c1 = p1;
            if (g < 7) {
                p0 = Mr[idx + 64];
                p1 = Mr[idx + 96];
            }
            float4 v0 = os4[idx];
            float4 v1 = os4[idx + 32];
            float t0 = fmaf(-S2, c0.x, v0.x);
            float t1 = fmaf(-S2, c0.y, v0.y);
            float t2 = fmaf(-S2, c0.z, v0.z);
            float t3 = fmaf(-S2, c0.w, v0.w);
            float t4 = fmaf(-S2, c1.x, v1.x);
            float t5 = fmaf(-S2, c1.y, v1.y);
            float t6 = fmaf(-S2, c1.z, v1.z);
            float t7 = fmaf(-S2, c1.w, v1.w);
            float mA = fmaxf(fmaxf(t0, t1), fmaxf(t2, t3));
            float n0 = fmaxf(m0, mA);
            s0 = s0 * ex2f(m0 - n0)
               + ((ex2f(t0 - n0) + ex2f(t1 - n0)) + (ex2f(t2 - n0) + ex2f(t3 - n0)));
            m0 = n0;
            float mB = fmaxf(fmaxf(t4, t5), fmaxf(t6, t7));
            float n1 = fmaxf(m1, mB);
            s1 = s1 * ex2f(m1 - n1)
               + ((ex2f(t4 - n1) + ex2f(t5 - n1)) + (ex2f(t6 - n1) + ex2f(t7 - n1)));
            m1 = n1;
        }
    }

    float m = fmaxf(m0, m1);
    float s = s0 * ex2f(m0 - m) + s1 * ex2f(m1 - m);
#pragma unroll
    for (int o = 16; o; o >>= 1) {
        float mo = __shfl_xor_sync(0xffffffffu, m, o);
        float so = __shfl_xor_sync(0xffffffffu, s, o);
        float nm = fmaxf(m, mo);
        s = s * ex2f(m - nm) + so * ex2f(mo - nm);
        m = nm;
    }
    if (l == 0) {
        float lse  = (m + lg2f(s)) * LN2;
        float pnew = EPSV * (LOG_MUV - lse);
        if (track_err) {
            float du = fabsf(pnew - mine[r]);
            atomicAdd(&blkerr, du);
        }
        mine[r] = pnew;
    }
    if (track_err) {
        __syncthreads();
        if (tid == 0) atomicAdd(&g_err[it], blkerr);
    }
}

// ---------------------------------------------------------------------------
// v-sweep: column LSE over C itself (R12 version, plain loads — hits land on
// the lines u pinned; u re-marks evict_last every iteration).
//   v_j = eps * (log_nu - lse_i((u_i - C_ij)/eps))
// Block = 512 threads (16 warps), 32 columns; warp w owns rows [w*128, +128).
// ---------------------------------------------------------------------------
__global__ void __launch_bounds__(512) k_vcol(const float* __restrict__ C, int it) {
    if (it > 0 && g_err[it - 1] < ERR_THRESH_SUM) return;

    __shared__ float uS2_s[NPTS];        // 8 KB : u * S2
    __shared__ float pm_s[16 * 32];
    __shared__ float ps_s[16 * 32];

    int blk = blockIdx.x;                // 512 blocks
    int b   = 7 - (blk >> 6);            // descending batches
    int jg  = blk & 63;                  // column group (32 cols)
    int tid = threadIdx.x;
    int w   = tid >> 5;
    int l   = tid & 31;

    const float4* ug  = reinterpret_cast<const float4*>(g_u + (b << 11));
    float4*       us4 = reinterpret_cast<float4*>(uS2_s);
    {
        float4 t = ug[tid];
        t.x *= S2; t.y *= S2; t.z *= S2; t.w *= S2;
        us4[tid] = t;
    }
    __syncthreads();

    int j = (jg << 5) + l;               // this thread's column
    const float* Cb = C + ((size_t)b << 22) + j;

    float m0 = -1e30f, s0 = 0.0f, m1 = -1e30f, s1 = 0.0f;
    int i0 = w << 7;                     // warp's 128-row segment
#pragma unroll 2
    for (int g = 0; g < 16; g++) {
        int i = i0 + (g << 3);
        const float* Ci = Cb + ((size_t)i << 11);
        float c0 = Ci[0];
        float c1 = Ci[(size_t)1 << 11];
        float c2 = Ci[(size_t)2 << 11];
        float c3 = Ci[(size_t)3 << 11];
        float c4 = Ci[(size_t)4 << 11];
        float c5 = Ci[(size_t)5 << 11];
        float c6 = Ci[(size_t)6 << 11];
        float c7 = Ci[(size_t)7 << 11];
        float t0 = fmaf(-S2, c0, uS2_s[i + 0]);
        float t1 = fmaf(-S2, c1, uS2_s[i + 1]);
        float t2 = fmaf(-S2, c2, uS2_s[i + 2]);
        float t3 = fmaf(-S2, c3, uS2_s[i + 3]);
        float t4 = fmaf(-S2, c4, uS2_s[i + 4]);
        float t5 = fmaf(-S2, c5, uS2_s[i + 5]);
        float t6 = fmaf(-S2, c6, uS2_s[i + 6]);
        float t7 = fmaf(-S2, c7, uS2_s[i + 7]);
        float mA = fmaxf(fmaxf(t0, t1), fmaxf(t2, t3));
        float n0 = fmaxf(m0, mA);
        s0 = s0 * ex2f(m0 - n0)
           + ((ex2f(t0 - n0) + ex2f(t1 - n0)) + (ex2f(t2 - n0) + ex2f(t3 - n0)));
        m0 = n0;
        float mB = fmaxf(fmaxf(t4, t5), fmaxf(t6, t7));
        float n1 = fmaxf(m1, mB);
        s1 = s1 * ex2f(m1 - n1)
           + ((ex2f(t4 - n1) + ex2f(t5 - n1)) + (ex2f(t6 - n1) + ex2f(t7 - n1)));
        m1 = n1;
    }
    float m = fmaxf(m0, m1);
    float s = s0 * ex2f(m0 - m) + s1 * ex2f(m1 - m);
    pm_s[(w << 5) + l] = m;
    ps_s[(w << 5) + l] = s;
    __syncthreads();

    if (w == 0) {
        float mm = pm_s[l], ss = ps_s[l];
#pragma unroll
        for (int k = 1; k < 16; k++) {
            float mo = pm_s[(k << 5) + l];
            float so = ps_s[(k << 5) + l];
            float nm = fmaxf(mm, mo);
            ss = ss * ex2f(mm - nm) + so * ex2f(mo - nm);
            mm = nm;
        }
        g_v[(b << 11) + j] = EPSV * (LOG_MUV - (mm + lg2f(ss)) * LN2);
    }
}

// ---------------------------------------------------------------------------
// Epilogue: pi = exp((u_i + v_j - C_ij)/eps), cost[b] = sum pi*C
// ---------------------------------------------------------------------------
__global__ void __launch_bounds__(256) k_pi(const float* __restrict__ C,
                                            float* __restrict__ pi,
                                            float* __restrict__ cost) {
    __shared__ float blkcost;
    if (threadIdx.x == 0) blkcost = 0.0f;
    __syncthreads();

    int warp = (blockIdx.x << 3) + (threadIdx.x >> 5);
    int lane = threadIdx.x & 31;
    int r = warp;
    int b = r >> 11;

    float u = g_u[r];
    const float4* Cr = reinterpret_cast<const float4*>(C + (size_t)r * NPTS);
    const float4* Vr = reinterpret_cast<const float4*>(g_v + (b << 11));
    float4* Pr = reinterpret_cast<float4*>(pi + (size_t)r * NPTS);

    float acc = 0.0f;
#pragma unroll 4
    for (int k = lane; k < NPTS / 4; k += 32) {
        float4 c = Cr[k];
        float4 v = Vr[k];
        float4 p;
        p.x = ex2f((u + v.x - c.x) * S2);
        p.y = ex2f((u + v.y - c.y) * S2);
        p.z = ex2f((u + v.z - c.z) * S2);
        p.w = ex2f((u + v.w - c.w) * S2);
        Pr[k] = p;
        acc += p.x * c.x + p.y * c.y + p.z * c.z + p.w * c.w;
    }
#pragma unroll
    for (int o = 16; o; o >>= 1) acc += __shfl_xor_sync(0xffffffffu, acc, o);
    if (lane == 0) atomicAdd(&blkcost, acc);
    __syncthreads();
    if (threadIdx.x == 0) atomicAdd(&cost[b], blkcost);
}

// ---------------------------------------------------------------------------
// Launch: init -> cost -> 100 x (u-sweep rows, v-sweep cols) -> pi.
// No dummy: the ncu capture slot (4th launch) lands on k_vcol(it=0) — the
// v kernel's first-ever profile.
// Output layout (tuple order): cost[8] | pi | C.
// ---------------------------------------------------------------------------
extern "C" void kernel_launch(void* const* d_in, const int* in_sizes, int n_in,
                              void* d_out, int out_size) {
    const float* x = (const float*)d_in[0];
    const float* y = (const float*)d_in[1];
    float* out  = (float*)d_out;
    float* cost = out;
    float* pi   = out + NBATCH;
    float* C    = out + NBATCH + NMAT;

    float* u;
    cudaGetSymbolAddress((void**)&u, g_u);
    float* v;
    cudaGetSymbolAddress((void**)&v, g_v);

    k_init<<<64, 256>>>(cost);
    k_cost<<<NBATCH * 32 * 32, 256>>>(x, y, C);
    for (int it = 0; it < MAX_IT; it++) {
        k_sweep<<<NROWS / 8, 256>>>(C, v, u, it, 1);   // u update (tracks err)
        k_vcol<<<512, 512>>>(C, it);                   // v update, column LSE
    }
    k_pi<<<NROWS / 8, 256>>>(C, pi, cost);
}